// round 11
// baseline (speedup 1.0000x reference)
#include <cuda_runtime.h>
#include <cuda_fp16.h>
#include <cstdint>

// Problem dims
#define BB 16
#define LL 50
#define PP 49
#define TT 20
#define DD 512
#define HH 8
#define DHD 64
#define DFF 2048
#define NBL (BB*LL)            // 800
#define M_IMG (NBL*TT)         // 16000
#define M_TIT (NBL*PP)         // 39200
#define M_IMG_PAD 16128        // 126*128
#define M_TIT_PAD 39424        // 308*128
#define M_ALL (M_IMG_PAD + M_TIT_PAD)   // 55552 = 434*128

// Weight offsets in half scratch
#define WOFF_P   0
#define WOFF_1I  262144
#define WOFF_2I  1310720
#define WOFF_1T  2359296
#define WOFF_2T  3407872
#define WTOTAL   4456448

// Scratch (zero-init; pad rows never written -> stay 0)
__device__ __half g_attn_h[(size_t)M_ALL*DD];
__device__ __half g_hid_h[(size_t)M_ALL*DD];
__device__ __half g_G_h  [(size_t)M_ALL*DFF];
__device__ __half g_F_h  [(size_t)M_ALL*DD];
__device__ __half g_Wh   [WTOTAL];

// ---------------------------------------------------------------------------
// helpers
// ---------------------------------------------------------------------------
__device__ __forceinline__ void cp16(void* s, const void* g) {
    unsigned sa = (unsigned)__cvta_generic_to_shared(s);
    asm volatile("cp.async.cg.shared.global [%0], [%1], 16;" :: "r"(sa), "l"(g));
}
__device__ __forceinline__ void ldm4(uint32_t* r, uint32_t addr) {
    asm volatile("ldmatrix.sync.aligned.m8n8.x4.shared.b16 {%0,%1,%2,%3}, [%4];"
        : "=r"(r[0]), "=r"(r[1]), "=r"(r[2]), "=r"(r[3]) : "r"(addr));
}
__device__ __forceinline__ void mma16816(float* d, const uint32_t* a, const uint32_t* b) {
    asm volatile(
        "mma.sync.aligned.m16n8k16.row.col.f32.f16.f16.f32 "
        "{%0,%1,%2,%3},{%4,%5,%6,%7},{%8,%9},{%0,%1,%2,%3};"
        : "+f"(d[0]), "+f"(d[1]), "+f"(d[2]), "+f"(d[3])
        : "r"(a[0]), "r"(a[1]), "r"(a[2]), "r"(a[3]), "r"(b[0]), "r"(b[1]));
}
// overflow-safe fast gelu-tanh (__expf based, rel err ~1e-6)
__device__ __forceinline__ float gelu_fast(float x) {
    float x2 = x*x;
    float u  = x*(0.79788456080286536f + 0.03567740814183493f*x2);
    float au = fabsf(u);
    float e  = __expf(-2.f*au);            // (0,1], no overflow
    float th = __fdividef(1.f - e, 1.f + e);
    th = copysignf(th, u);
    return 0.5f*x*(1.f + th);
}

// ---------------------------------------------------------------------------
// fused fp32 -> fp16 convert for all 5 weight matrices
// ---------------------------------------------------------------------------
__global__ void __launch_bounds__(256) f2h_all_kernel(
    const float* __restrict__ wp, const float* __restrict__ w1i,
    const float* __restrict__ w2i, const float* __restrict__ w1t,
    const float* __restrict__ w2t, __half* __restrict__ d)
{
    int idx = (blockIdx.x*256 + threadIdx.x) * 4;
    if (idx >= WTOTAL) return;
    const float* s;
    int local;
    if (idx < WOFF_1I)      { s = wp;  local = idx - WOFF_P;  }
    else if (idx < WOFF_2I) { s = w1i; local = idx - WOFF_1I; }
    else if (idx < WOFF_1T) { s = w2i; local = idx - WOFF_2I; }
    else if (idx < WOFF_2T) { s = w1t; local = idx - WOFF_1T; }
    else                    { s = w2t; local = idx - WOFF_2T; }
    float4 v = *(const float4*)(s + local);
    __half2* p = (__half2*)(d + idx);
    p[0] = __floats2half2_rn(v.x, v.y);
    p[1] = __floats2half2_rn(v.z, v.w);
}

// ---------------------------------------------------------------------------
// Attention kernel: one block per (bl, h). fp32 math, half outputs.
// ---------------------------------------------------------------------------
__global__ void __launch_bounds__(256) attn_kernel(
    const float* __restrict__ img, const float* __restrict__ tit,
    const int* __restrict__ mask,
    const float* __restrict__ scale_img, const float* __restrict__ scale_tit,
    __half* __restrict__ attnI, __half* __restrict__ attnT)
{
    __shared__ float simg[PP][DHD+1];
    __shared__ float stit[TT][DHD+1];
    __shared__ float raw[PP][TT];
    __shared__ float pimg[PP][TT];
    __shared__ float ptit[TT][PP];
    __shared__ float sci[PP];
    __shared__ float sct[TT];
    __shared__ int   smask[TT];

    int bl = blockIdx.x >> 3;
    int h  = blockIdx.x & 7;
    int tid = threadIdx.x;

    const float* ib = img + (size_t)bl*PP*DD + h*DHD;
    const float* tb = tit + (size_t)bl*TT*DD + h*DHD;

    for (int i = tid; i < PP*DHD; i += 256) { int p=i>>6, d=i&63; simg[p][d] = ib[p*DD+d]; }
    for (int i = tid; i < TT*DHD; i += 256) { int t=i>>6, d=i&63; stit[t][d] = tb[t*DD+d]; }
    if (tid < TT) { smask[tid] = mask[bl*TT+tid]; sct[tid] = scale_tit[h*TT+tid]; }
    if (tid >= 64 && tid < 64+PP) sci[tid-64] = scale_img[h*PP + (tid-64)];
    __syncthreads();

    for (int i = tid; i < PP*TT; i += 256) {
        int p = i / TT, t = i - p*TT;
        float s = 0.f;
        #pragma unroll
        for (int d = 0; d < DHD; d++) s += simg[p][d]*stit[t][d];
        raw[p][t] = s * 0.125f;
    }
    __syncthreads();

    if (tid < PP) {
        int p = tid; float sc = sci[p];
        float v[TT]; float mx = -INFINITY;
        #pragma unroll
        for (int t = 0; t < TT; t++) { v[t] = smask[t] ? raw[p][t]*sc : -1e9f; mx = fmaxf(mx, v[t]); }
        float sum = 0.f;
        #pragma unroll
        for (int t = 0; t < TT; t++) { v[t] = __expf(v[t]-mx); sum += v[t]; }
        float inv = 1.f/sum;
        #pragma unroll
        for (int t = 0; t < TT; t++) pimg[p][t] = v[t]*inv;
    } else if (tid >= 64 && tid < 64+TT) {
        int t = tid-64; float sc = sct[t];
        if (smask[t]) {
            float mx = -INFINITY;
            for (int p = 0; p < PP; p++) mx = fmaxf(mx, raw[p][t]*sc);
            float sum = 0.f;
            for (int p = 0; p < PP; p++) { float e = __expf(raw[p][t]*sc - mx); ptit[t][p] = e; sum += e; }
            float inv = 1.f/sum;
            for (int p = 0; p < PP; p++) ptit[t][p] *= inv;
        } else {
            float u = 1.0f/(float)PP;
            for (int p = 0; p < PP; p++) ptit[t][p] = u;
        }
    }
    __syncthreads();

    for (int i = tid; i < TT*DHD; i += 256) {
        int t = i>>6, d = i&63;
        float s = 0.f;
        #pragma unroll
        for (int p = 0; p < PP; p++) s += ptit[t][p]*simg[p][d];
        attnI[((size_t)bl*TT + t)*DD + h*DHD + d] = __float2half_rn(s);
    }
    for (int i = tid; i < PP*DHD; i += 256) {
        int p = i>>6, d = i&63;
        float s = 0.f;
        #pragma unroll
        for (int t = 0; t < TT; t++) s += pimg[p][t]*stit[t][d];
        attnT[((size_t)bl*PP + p)*DD + h*DHD + d] = __float2half_rn(s);
    }
}

// ---------------------------------------------------------------------------
// fp16 mma.sync GEMM with per-row-block weight select:
//   C[M,N] = A[M,K] @ Wsel[N,K]^T + bias_sel   (Wsel = Wa if m0<Mswitch else Wb)
// Block 128x128, 8 warps (2x4), warp tile 64x32 (4x4 of m16n8k16). BK=64,
// 3-stage cp.async ring, 128B-row swizzle, ldmatrix.x4 with precomputed
// xor terms, 2 CTAs/SM. K is compile-time. M%128==0, N%128==0.
// ---------------------------------------------------------------------------
#define GBM 128
#define GBN 128
#define GBK 64
#define STG_B 32768u                 // A 16KB + B 16KB per stage
#define NSTAGE 3
#define GSMEM_BYTES (NSTAGE*STG_B)   // 98304

__device__ __forceinline__ void fill_stage(char* sbase,
    const __half* __restrict__ Ag, const __half* __restrict__ Wg,
    int kcol, int K, int tid)
{
    // A: 128 rows x 8 granules (16B = 8 halves)
    #pragma unroll
    for (int i = 0; i < 4; i++) {
        int id = tid + i*256;
        int r = id >> 3, g = id & 7;
        uint32_t off = (uint32_t)((r*8 + (g ^ (r & 7))) << 4);
        cp16(sbase + off, Ag + (size_t)r*K + kcol + g*8);
    }
    // B: 128 rows x 8 granules
    #pragma unroll
    for (int i = 0; i < 4; i++) {
        int id = tid + i*256;
        int r = id >> 3, g = id & 7;
        uint32_t off = 16384u + (uint32_t)((r*8 + (g ^ (r & 7))) << 4);
        cp16(sbase + off, Wg + (size_t)r*K + kcol + g*8);
    }
    asm volatile("cp.async.commit_group;" ::: "memory");
}

template<int KT, int GELU_EPI>
__global__ void __launch_bounds__(256, 2) gemm_h(
    const __half* __restrict__ A,
    const __half* __restrict__ Wa, const __half* __restrict__ Wb,
    const float* __restrict__ ba,  const float* __restrict__ bb,
    __half* __restrict__ Ch, int Mswitch, int N)
{
    extern __shared__ __align__(1024) char sm[];
    uint32_t smem_base = (uint32_t)__cvta_generic_to_shared(sm);

    constexpr int nk = KT / GBK;

    int tid  = threadIdx.x;
    int warp = tid >> 5, lane = tid & 31;
    int wm = warp >> 2, wn = warp & 3;       // 2x4 warps of 64x32
    int q  = lane >> 2, t = lane & 3;
    long m0 = (long)blockIdx.y * GBM;
    long n0 = (long)blockIdx.x * GBN;

    const __half* Wsel  = (m0 >= Mswitch) ? Wb : Wa;
    const float*  bias  = (m0 >= Mswitch) ? bb : ba;

    const __half* Ag = A    + m0*(long)KT;
    const __half* Wg = Wsel + n0*(long)KT;

    // per-lane ldmatrix address components
    int a_rl = lane & 15;                          // row within 16-row tile
    int a_gs = lane >> 4;                          // k-granule select (0/1)
    int b_nl = (lane & 7) | ((lane & 16) >> 1);    // n within 16-col tile
    int b_gs = (lane >> 3) & 1;

    // precomputed xor terms per k16-step and lane bases
    uint32_t xa[4], xb[4];
    #pragma unroll
    for (int ks = 0; ks < 4; ks++) {
        xa[ks] = (uint32_t)(((ks*2 + a_gs) ^ (a_rl & 7)) << 4);
        xb[ks] = (uint32_t)(((ks*2 + b_gs) ^ (b_nl & 7)) << 4);
    }
    uint32_t aBase = (uint32_t)((wm*64 + a_rl) * 128);
    uint32_t bBase = 16384u + (uint32_t)((wn*32 + b_nl) * 128);

    float acc[4][4][4];
    #pragma unroll
    for (int mi = 0; mi < 4; mi++)
        #pragma unroll
        for (int ni = 0; ni < 4; ni++)
            #pragma unroll
            for (int e = 0; e < 4; e++) acc[mi][ni][e] = 0.f;

    // prologue: fill stages 0,1 (k-blocks 0,1)
    fill_stage(sm + 0*STG_B, Ag, Wg, 0*GBK, KT, tid);
    fill_stage(sm + 1*STG_B, Ag, Wg, 1*GBK, KT, tid);

    int stg = 0;   // stage slot of kt
    for (int kt = 0; kt < nk; kt++) {
        if (kt == nk-1) { asm volatile("cp.async.wait_group 0;" ::: "memory"); }
        else            { asm volatile("cp.async.wait_group 1;" ::: "memory"); }
        __syncthreads();    // orders prior iter's reads before refill of that slot

        uint32_t sa = smem_base + (uint32_t)stg*STG_B;
        uint32_t aB = sa + aBase;
        uint32_t bB = sa + bBase;

        // frag loads for ks=0 FIRST, so mma can start while cp.asyncs issue
        uint32_t a[4][4], b[2][4];
        {
            uint32_t adA = aB + xa[0];
            uint32_t adB = bB + xb[0];
            #pragma unroll
            for (int mi = 0; mi < 4; mi++) ldm4(a[mi], adA + mi*2048);
            #pragma unroll
            for (int j = 0; j < 2; j++)    ldm4(b[j],  adB + j*2048);
        }

        if (kt + 2 < nk) {
            int s2 = stg + 2; if (s2 >= NSTAGE) s2 -= NSTAGE;
            fill_stage(sm + s2*STG_B, Ag, Wg, (kt+2)*GBK, KT, tid);
        }

        #pragma unroll
        for (int ks = 0; ks < 4; ks++) {
            if (ks > 0) {
                uint32_t adA = aB + xa[ks];
                uint32_t adB = bB + xb[ks];
                #pragma unroll
                for (int mi = 0; mi < 4; mi++) ldm4(a[mi], adA + mi*2048);
                #pragma unroll
                for (int j = 0; j < 2; j++)    ldm4(b[j],  adB + j*2048);
            }
            #pragma unroll
            for (int mi = 0; mi < 4; mi++)
                #pragma unroll
                for (int ni = 0; ni < 4; ni++)
                    mma16816(acc[mi][ni], a[mi], &b[ni>>1][(ni&1)*2]);
        }
        stg++; if (stg >= NSTAGE) stg -= NSTAGE;
    }

    // Epilogue: bias (+fast gelu), half2 stores
    #pragma unroll
    for (int mi = 0; mi < 4; mi++) {
        long r0 = m0 + wm*64 + mi*16 + q;
        #pragma unroll
        for (int ni = 0; ni < 4; ni++) {
            long cc = n0 + wn*32 + ni*8 + t*2;
            float bx = bias[cc], by = bias[cc+1];
            float v00 = acc[mi][ni][0] + bx, v01 = acc[mi][ni][1] + by;
            float v10 = acc[mi][ni][2] + bx, v11 = acc[mi][ni][3] + by;
            if (GELU_EPI) {
                v00 = gelu_fast(v00); v01 = gelu_fast(v01);
                v10 = gelu_fast(v10); v11 = gelu_fast(v11);
            }
            *(__half2*)(Ch + r0*(long)N + cc)     = __floats2half2_rn(v00, v01);
            *(__half2*)(Ch + (r0+8)*(long)N + cc) = __floats2half2_rn(v10, v11);
        }
    }
}

// ---------------------------------------------------------------------------
// Fused LayerNorm (ddof=1) + residual for BOTH streams, half inputs.
// grid = M_IMG + M_TIT rows; out rows are contiguous (img then tit).
// ---------------------------------------------------------------------------
__global__ void __launch_bounds__(128) ln_res_all_kernel(
    const __half* __restrict__ F, const __half* __restrict__ hid,
    const float* __restrict__ a_img, const float* __restrict__ b_img,
    const float* __restrict__ a_tit, const float* __restrict__ b_tit,
    float* __restrict__ out)
{
    int row = blockIdx.x;
    const float* aP; const float* bP;
    size_t srow;
    if (row < M_IMG) { aP = a_img; bP = b_img; srow = (size_t)row; }
    else             { aP = a_tit; bP = b_tit; srow = (size_t)M_IMG_PAD + (row - M_IMG); }

    const __half2* x2 = (const __half2*)(F   + srow*DD);
    const __half2* h2 = (const __half2*)(hid + srow*DD);
    int tid = threadIdx.x;

    float2 v0 = __half22float2(x2[tid]);
    float2 v1 = __half22float2(x2[tid + 128]);
    float s  = v0.x + v0.y + v1.x + v1.y;
    float ss = v0.x*v0.x + v0.y*v0.y + v1.x*v1.x + v1.y*v1.y;
    #pragma unroll
    for (int o = 16; o; o >>= 1) { s += __shfl_xor_sync(~0u, s, o); ss += __shfl_xor_sync(~0u, ss, o); }
    __shared__ float sh[8];
    if ((tid & 31) == 0) { sh[tid>>5] = s; sh[4 + (tid>>5)] = ss; }
    __syncthreads();
    s  = sh[0]+sh[1]+sh[2]+sh[3];
    ss = sh[4]+sh[5]+sh[6]+sh[7];
    float mean = s * (1.f/512.f);
    float var  = fmaxf((ss - 512.f*mean*mean) * (1.f/511.f), 0.f);
    float inv  = 1.f/(sqrtf(var) + 1e-6f);

    float2 hh0 = __half22float2(h2[tid]);
    float2 hh1 = __half22float2(h2[tid + 128]);
    const float2* a2 = (const float2*)aP;
    const float2* b2 = (const float2*)bP;
    float2 A0 = a2[tid], A1 = a2[tid+128];
    float2 B0 = b2[tid], B1 = b2[tid+128];

    float2* o2 = (float2*)(out + (size_t)row*DD);
    o2[tid]     = make_float2(hh0.x + A0.x*(v0.x-mean)*inv + B0.x,
                              hh0.y + A0.y*(v0.y-mean)*inv + B0.y);
    o2[tid+128] = make_float2(hh1.x + A1.x*(v1.x-mean)*inv + B1.x,
                              hh1.y + A1.y*(v1.y-mean)*inv + B1.y);
}

// ---------------------------------------------------------------------------
// Launch
// ---------------------------------------------------------------------------
extern "C" void kernel_launch(void* const* d_in, const int* in_sizes, int n_in,
                              void* d_out, int out_size)
{
    const float* img         = (const float*)d_in[0];
    const float* title       = (const float*)d_in[1];
    const int*   mask        = (const int*)  d_in[2];
    const float* scale_img   = (const float*)d_in[3];
    const float* scale_title = (const float*)d_in[4];
    const float* w_proj      = (const float*)d_in[5];
    const float* b_proj      = (const float*)d_in[6];
    const float* w1_img      = (const float*)d_in[7];
    const float* b1_img      = (const float*)d_in[8];
    const float* w2_img      = (const float*)d_in[9];
    const float* b2_img      = (const float*)d_in[10];
    const float* w1_tit      = (const float*)d_in[11];
    const float* b1_tit      = (const float*)d_in[12];
    const float* w2_tit      = (const float*)d_in[13];
    const float* b2_tit      = (const float*)d_in[14];
    const float* ln_a_img    = (const float*)d_in[15];
    const float* ln_b_img    = (const float*)d_in[16];
    const float* ln_a_tit    = (const float*)d_in[17];
    const float* ln_b_tit    = (const float*)d_in[18];
    float* out = (float*)d_out;

    __half *attn_h, *hid_h, *G_h, *F_h, *Wh;
    cudaGetSymbolAddress((void**)&attn_h, g_attn_h);
    cudaGetSymbolAddress((void**)&hid_h,  g_hid_h);
    cudaGetSymbolAddress((void**)&G_h,    g_G_h);
    cudaGetSymbolAddress((void**)&F_h,    g_F_h);
    cudaGetSymbolAddress((void**)&Wh,     g_Wh);

    cudaFuncSetAttribute(gemm_h<512,0>,  cudaFuncAttributeMaxDynamicSharedMemorySize, GSMEM_BYTES);
    cudaFuncSetAttribute(gemm_h<512,1>,  cudaFuncAttributeMaxDynamicSharedMemorySize, GSMEM_BYTES);
    cudaFuncSetAttribute(gemm_h<2048,0>, cudaFuncAttributeMaxDynamicSharedMemorySize, GSMEM_BYTES);

    // convert all weights to half (single launch)
    f2h_all_kernel<<<(WTOTAL/4+255)/256, 256>>>(w_proj, w1_img, w2_img, w1_tit, w2_tit, Wh);

    __half* attnI = attn_h;
    __half* attnT = attn_h + (size_t)M_IMG_PAD*DD;

    attn_kernel<<<NBL*HH, 256>>>(img, title, mask, scale_img, scale_title, attnI, attnT);

    // proj for both streams (same weights both sides of the switch)
    gemm_h<512,0><<<dim3(DD/GBN, M_ALL/GBM), 256, GSMEM_BYTES>>>(
        attn_h, Wh+WOFF_P, Wh+WOFF_P, b_proj, b_proj, hid_h, M_ALL, DD);

    // ffn1 for BOTH streams in one launch (weight select at row M_IMG_PAD)
    gemm_h<512,1><<<dim3(DFF/GBN, M_ALL/GBM), 256, GSMEM_BYTES>>>(
        hid_h, Wh+WOFF_1I, Wh+WOFF_1T, b1_img, b1_tit, G_h, M_IMG_PAD, DFF);

    // ffn2 for BOTH streams in one launch
    gemm_h<2048,0><<<dim3(DD/GBN, M_ALL/GBM), 256, GSMEM_BYTES>>>(
        G_h, Wh+WOFF_2I, Wh+WOFF_2T, b2_img, b2_tit, F_h, M_IMG_PAD, DD);

    // fused LN + residual for both streams -> outputs
    ln_res_all_kernel<<<M_IMG + M_TIT, 128>>>(F_h, hid_h,
        ln_a_img, ln_b_img, ln_a_tit, ln_b_tit, out);
}

// round 12
// speedup vs baseline: 1.0709x; 1.0709x over previous
#include <cuda_runtime.h>
#include <cuda_fp16.h>
#include <cstdint>

// Problem dims
#define BB 16
#define LL 50
#define PP 49
#define TT 20
#define DD 512
#define HH 8
#define DHD 64
#define DFF 2048
#define NBL (BB*LL)            // 800
#define M_IMG (NBL*TT)         // 16000
#define M_TIT (NBL*PP)         // 39200
#define M_IMG_PAD 16128        // 126*128
#define M_TIT_PAD 39424        // 308*128
#define M_ALL (M_IMG_PAD + M_TIT_PAD)   // 55552 = 434*128

// Weight offsets in half scratch
#define WOFF_P   0
#define WOFF_1I  262144
#define WOFF_2I  1310720
#define WOFF_1T  2359296
#define WOFF_2T  3407872
#define WTOTAL   4456448

// Scratch (zero-init; pad rows never written -> stay 0)
__device__ __half g_attn_h[(size_t)M_ALL*DD];
__device__ __half g_hid_h[(size_t)M_ALL*DD];
__device__ __half g_G_h  [(size_t)M_ALL*DFF];
__device__ __half g_F_h  [(size_t)M_ALL*DD];
__device__ __half g_Wh   [WTOTAL];

// ---------------------------------------------------------------------------
// helpers
// ---------------------------------------------------------------------------
__device__ __forceinline__ void cpa(uint32_t sa, const void* g) {
    asm volatile("cp.async.cg.shared.global [%0], [%1], 16;" :: "r"(sa), "l"(g));
}
__device__ __forceinline__ void ldm4(uint32_t* r, uint32_t addr) {
    asm volatile("ldmatrix.sync.aligned.m8n8.x4.shared.b16 {%0,%1,%2,%3}, [%4];"
        : "=r"(r[0]), "=r"(r[1]), "=r"(r[2]), "=r"(r[3]) : "r"(addr));
}
__device__ __forceinline__ void mma16816(float* d, const uint32_t* a, const uint32_t* b) {
    asm volatile(
        "mma.sync.aligned.m16n8k16.row.col.f32.f16.f16.f32 "
        "{%0,%1,%2,%3},{%4,%5,%6,%7},{%8,%9},{%0,%1,%2,%3};"
        : "+f"(d[0]), "+f"(d[1]), "+f"(d[2]), "+f"(d[3])
        : "r"(a[0]), "r"(a[1]), "r"(a[2]), "r"(a[3]), "r"(b[0]), "r"(b[1]));
}
// overflow-safe fast gelu-tanh (__expf based, rel err ~1e-6)
__device__ __forceinline__ float gelu_fast(float x) {
    float x2 = x*x;
    float u  = x*(0.79788456080286536f + 0.03567740814183493f*x2);
    float au = fabsf(u);
    float e  = __expf(-2.f*au);            // (0,1], no overflow
    float th = __fdividef(1.f - e, 1.f + e);
    th = copysignf(th, u);
    return 0.5f*x*(1.f + th);
}

// ---------------------------------------------------------------------------
// fused fp32 -> fp16 convert for all 5 weight matrices
// ---------------------------------------------------------------------------
__global__ void __launch_bounds__(256) f2h_all_kernel(
    const float* __restrict__ wp, const float* __restrict__ w1i,
    const float* __restrict__ w2i, const float* __restrict__ w1t,
    const float* __restrict__ w2t, __half* __restrict__ d)
{
    int idx = (blockIdx.x*256 + threadIdx.x) * 4;
    if (idx >= WTOTAL) return;
    const float* s;
    int local;
    if (idx < WOFF_1I)      { s = wp;  local = idx - WOFF_P;  }
    else if (idx < WOFF_2I) { s = w1i; local = idx - WOFF_1I; }
    else if (idx < WOFF_1T) { s = w2i; local = idx - WOFF_2I; }
    else if (idx < WOFF_2T) { s = w1t; local = idx - WOFF_1T; }
    else                    { s = w2t; local = idx - WOFF_2T; }
    float4 v = *(const float4*)(s + local);
    __half2* p = (__half2*)(d + idx);
    p[0] = __floats2half2_rn(v.x, v.y);
    p[1] = __floats2half2_rn(v.z, v.w);
}

// ---------------------------------------------------------------------------
// Attention kernel: one block per (bl, h). fp32 math, half outputs.
// ---------------------------------------------------------------------------
__global__ void __launch_bounds__(256) attn_kernel(
    const float* __restrict__ img, const float* __restrict__ tit,
    const int* __restrict__ mask,
    const float* __restrict__ scale_img, const float* __restrict__ scale_tit,
    __half* __restrict__ attnI, __half* __restrict__ attnT)
{
    __shared__ float simg[PP][DHD+1];
    __shared__ float stit[TT][DHD+1];
    __shared__ float raw[PP][TT];
    __shared__ float pimg[PP][TT];
    __shared__ float ptit[TT][PP];
    __shared__ float sci[PP];
    __shared__ float sct[TT];
    __shared__ int   smask[TT];

    int bl = blockIdx.x >> 3;
    int h  = blockIdx.x & 7;
    int tid = threadIdx.x;

    const float* ib = img + (size_t)bl*PP*DD + h*DHD;
    const float* tb = tit + (size_t)bl*TT*DD + h*DHD;

    for (int i = tid; i < PP*DHD; i += 256) { int p=i>>6, d=i&63; simg[p][d] = ib[p*DD+d]; }
    for (int i = tid; i < TT*DHD; i += 256) { int t=i>>6, d=i&63; stit[t][d] = tb[t*DD+d]; }
    if (tid < TT) { smask[tid] = mask[bl*TT+tid]; sct[tid] = scale_tit[h*TT+tid]; }
    if (tid >= 64 && tid < 64+PP) sci[tid-64] = scale_img[h*PP + (tid-64)];
    __syncthreads();

    for (int i = tid; i < PP*TT; i += 256) {
        int p = i / TT, t = i - p*TT;
        float s = 0.f;
        #pragma unroll
        for (int d = 0; d < DHD; d++) s += simg[p][d]*stit[t][d];
        raw[p][t] = s * 0.125f;
    }
    __syncthreads();

    if (tid < PP) {
        int p = tid; float sc = sci[p];
        float v[TT]; float mx = -INFINITY;
        #pragma unroll
        for (int t = 0; t < TT; t++) { v[t] = smask[t] ? raw[p][t]*sc : -1e9f; mx = fmaxf(mx, v[t]); }
        float sum = 0.f;
        #pragma unroll
        for (int t = 0; t < TT; t++) { v[t] = __expf(v[t]-mx); sum += v[t]; }
        float inv = 1.f/sum;
        #pragma unroll
        for (int t = 0; t < TT; t++) pimg[p][t] = v[t]*inv;
    } else if (tid >= 64 && tid < 64+TT) {
        int t = tid-64; float sc = sct[t];
        if (smask[t]) {
            float mx = -INFINITY;
            for (int p = 0; p < PP; p++) mx = fmaxf(mx, raw[p][t]*sc);
            float sum = 0.f;
            for (int p = 0; p < PP; p++) { float e = __expf(raw[p][t]*sc - mx); ptit[t][p] = e; sum += e; }
            float inv = 1.f/sum;
            for (int p = 0; p < PP; p++) ptit[t][p] *= inv;
        } else {
            float u = 1.0f/(float)PP;
            for (int p = 0; p < PP; p++) ptit[t][p] = u;
        }
    }
    __syncthreads();

    for (int i = tid; i < TT*DHD; i += 256) {
        int t = i>>6, d = i&63;
        float s = 0.f;
        #pragma unroll
        for (int p = 0; p < PP; p++) s += ptit[t][p]*simg[p][d];
        attnI[((size_t)bl*TT + t)*DD + h*DHD + d] = __float2half_rn(s);
    }
    for (int i = tid; i < PP*DHD; i += 256) {
        int p = i>>6, d = i&63;
        float s = 0.f;
        #pragma unroll
        for (int t = 0; t < TT; t++) s += pimg[p][t]*stit[t][d];
        attnT[((size_t)bl*PP + p)*DD + h*DHD + d] = __float2half_rn(s);
    }
}

// ---------------------------------------------------------------------------
// fp16 mma.sync GEMM with per-row-block weight select:
//   C[M,N] = A[M,K] @ Wsel[N,K]^T + bias_sel   (Wsel = Wa if m0<Mswitch else Wb)
// Block 128x128, 8 warps (2x4), warp tile 64x32 (4x4 of m16n8k16). BK=64,
// 3-stage cp.async ring, 128B-row swizzle, ldmatrix.x4, 2 CTAs/SM.
// Register-diet version: 32-bit addressing, frag arrays declared per-step
// so ptxas can rename/pipeline them. K compile-time. M%128==0, N%128==0.
// ---------------------------------------------------------------------------
#define GBM 128
#define GBN 128
#define GBK 64
#define STG_B 32768u                 // A 16KB + B 16KB per stage
#define NSTAGE 3
#define GSMEM_BYTES (NSTAGE*STG_B)   // 98304

template<int KT>
__device__ __forceinline__ void fill_stage(uint32_t sdst,
    const __half* fA, const __half* fW, uint32_t foff, int kcol)
{
    #pragma unroll
    for (int i = 0; i < 4; i++) {
        cpa(sdst + foff + i*4096u,            fA + kcol + i*32*KT);
        cpa(sdst + 16384u + foff + i*4096u,   fW + kcol + i*32*KT);
    }
    asm volatile("cp.async.commit_group;" ::: "memory");
}

template<int KT, int GELU_EPI>
__global__ void __launch_bounds__(256, 2) gemm_h(
    const __half* __restrict__ A,
    const __half* __restrict__ Wa, const __half* __restrict__ Wb,
    const float* __restrict__ ba,  const float* __restrict__ bb,
    __half* __restrict__ Ch, int Mswitch, int N)
{
    extern __shared__ __align__(1024) char sm[];
    uint32_t smem_base = (uint32_t)__cvta_generic_to_shared(sm);
    constexpr int nk = KT / GBK;

    int tid  = threadIdx.x;
    int warp = tid >> 5, lane = tid & 31;
    int wm = warp >> 2, wn = warp & 3;       // 2x4 warps of 64x32
    int m0i = blockIdx.y * GBM;
    int n0i = blockIdx.x * GBN;

    const __half* Ag = A + (size_t)m0i*KT;
    const __half* Wg = ((m0i >= Mswitch) ? Wb : Wa) + (size_t)n0i*KT;

    // fill-lane constants
    int fr = tid >> 3, fg = tid & 7;
    uint32_t foff = (uint32_t)((fr*8 + (fg ^ (fr & 7))) << 4);
    const __half* fA = Ag + fr*KT + fg*8;
    const __half* fW = Wg + fr*KT + fg*8;

    // ldmatrix lane constants, bases folded into xor terms
    int a_rl = lane & 15;
    int a_gs = lane >> 4;
    int b_nl = (lane & 7) | ((lane & 16) >> 1);
    int b_gs = (lane >> 3) & 1;
    uint32_t xa[4], xb[4];
    #pragma unroll
    for (int ks = 0; ks < 4; ks++) {
        xa[ks] = (uint32_t)((wm*64 + a_rl)*128) +
                 (uint32_t)((((ks*2 + a_gs) ^ (a_rl & 7))) << 4);
        xb[ks] = 16384u + (uint32_t)((wn*32 + b_nl)*128) +
                 (uint32_t)((((ks*2 + b_gs) ^ (b_nl & 7))) << 4);
    }

    float acc[4][4][4];
    #pragma unroll
    for (int mi = 0; mi < 4; mi++)
        #pragma unroll
        for (int ni = 0; ni < 4; ni++)
            #pragma unroll
            for (int e = 0; e < 4; e++) acc[mi][ni][e] = 0.f;

    // prologue: stages 0,1 (k-blocks 0,1)
    fill_stage<KT>(smem_base,          fA, fW, foff, 0);
    fill_stage<KT>(smem_base + STG_B,  fA, fW, foff, GBK);

    uint32_t stgoff = 0;
    for (int kt = 0; kt < nk; kt++) {
        if (kt == nk-1) { asm volatile("cp.async.wait_group 0;" ::: "memory"); }
        else            { asm volatile("cp.async.wait_group 1;" ::: "memory"); }
        __syncthreads();    // orders prior iter's reads before refill of that slot

        if (kt + 2 < nk) {
            uint32_t s2 = (stgoff >= STG_B) ? (stgoff - STG_B) : (stgoff + 2u*STG_B);
            fill_stage<KT>(smem_base + s2, fA, fW, foff, (kt+2)*GBK);
        }

        uint32_t sbase = smem_base + stgoff;
        #pragma unroll
        for (int ks = 0; ks < 4; ks++) {
            uint32_t a[4][4], b[2][4];
            #pragma unroll
            for (int mi = 0; mi < 4; mi++) ldm4(a[mi], sbase + xa[ks] + mi*2048u);
            #pragma unroll
            for (int j = 0; j < 2; j++)    ldm4(b[j],  sbase + xb[ks] + j*2048u);
            #pragma unroll
            for (int mi = 0; mi < 4; mi++)
                #pragma unroll
                for (int ni = 0; ni < 4; ni++)
                    mma16816(acc[mi][ni], a[mi], &b[ni>>1][(ni&1)*2]);
        }
        stgoff += STG_B; if (stgoff >= NSTAGE*STG_B) stgoff = 0;
    }

    // Epilogue: bias (+fast gelu), half2 stores, 32-bit indexing
    const float* bias = (m0i >= Mswitch) ? bb : ba;
    int q = lane >> 2, t = lane & 3;
    uint32_t rbase = (uint32_t)(m0i + wm*64 + q);
    uint32_t cbase = (uint32_t)(n0i + wn*32 + t*2);
    #pragma unroll
    for (int mi = 0; mi < 4; mi++) {
        uint32_t r0 = rbase + mi*16;
        #pragma unroll
        for (int ni = 0; ni < 4; ni++) {
            uint32_t cc = cbase + ni*8;
            float bx = bias[cc], by = bias[cc+1];
            float v00 = acc[mi][ni][0] + bx, v01 = acc[mi][ni][1] + by;
            float v10 = acc[mi][ni][2] + bx, v11 = acc[mi][ni][3] + by;
            if (GELU_EPI) {
                v00 = gelu_fast(v00); v01 = gelu_fast(v01);
                v10 = gelu_fast(v10); v11 = gelu_fast(v11);
            }
            uint32_t off = r0*(uint32_t)N + cc;
            *(__half2*)(Ch + off)                 = __floats2half2_rn(v00, v01);
            *(__half2*)(Ch + off + 8u*(uint32_t)N) = __floats2half2_rn(v10, v11);
        }
    }
}

// ---------------------------------------------------------------------------
// Fused LayerNorm (ddof=1) + residual for BOTH streams, half inputs.
// grid = M_IMG + M_TIT rows; out rows are contiguous (img then tit).
// ---------------------------------------------------------------------------
__global__ void __launch_bounds__(128) ln_res_all_kernel(
    const __half* __restrict__ F, const __half* __restrict__ hid,
    const float* __restrict__ a_img, const float* __restrict__ b_img,
    const float* __restrict__ a_tit, const float* __restrict__ b_tit,
    float* __restrict__ out)
{
    int row = blockIdx.x;
    const float* aP; const float* bP;
    size_t srow;
    if (row < M_IMG) { aP = a_img; bP = b_img; srow = (size_t)row; }
    else             { aP = a_tit; bP = b_tit; srow = (size_t)M_IMG_PAD + (row - M_IMG); }

    const __half2* x2 = (const __half2*)(F   + srow*DD);
    const __half2* h2 = (const __half2*)(hid + srow*DD);
    int tid = threadIdx.x;

    float2 v0 = __half22float2(x2[tid]);
    float2 v1 = __half22float2(x2[tid + 128]);
    float s  = v0.x + v0.y + v1.x + v1.y;
    float ss = v0.x*v0.x + v0.y*v0.y + v1.x*v1.x + v1.y*v1.y;
    #pragma unroll
    for (int o = 16; o; o >>= 1) { s += __shfl_xor_sync(~0u, s, o); ss += __shfl_xor_sync(~0u, ss, o); }
    __shared__ float sh[8];
    if ((tid & 31) == 0) { sh[tid>>5] = s; sh[4 + (tid>>5)] = ss; }
    __syncthreads();
    s  = sh[0]+sh[1]+sh[2]+sh[3];
    ss = sh[4]+sh[5]+sh[6]+sh[7];
    float mean = s * (1.f/512.f);
    float var  = fmaxf((ss - 512.f*mean*mean) * (1.f/511.f), 0.f);
    float inv  = 1.f/(sqrtf(var) + 1e-6f);

    float2 hh0 = __half22float2(h2[tid]);
    float2 hh1 = __half22float2(h2[tid + 128]);
    const float2* a2 = (const float2*)aP;
    const float2* b2 = (const float2*)bP;
    float2 A0 = a2[tid], A1 = a2[tid+128];
    float2 B0 = b2[tid], B1 = b2[tid+128];

    float2* o2 = (float2*)(out + (size_t)row*DD);
    o2[tid]     = make_float2(hh0.x + A0.x*(v0.x-mean)*inv + B0.x,
                              hh0.y + A0.y*(v0.y-mean)*inv + B0.y);
    o2[tid+128] = make_float2(hh1.x + A1.x*(v1.x-mean)*inv + B1.x,
                              hh1.y + A1.y*(v1.y-mean)*inv + B1.y);
}

// ---------------------------------------------------------------------------
// Launch
// ---------------------------------------------------------------------------
extern "C" void kernel_launch(void* const* d_in, const int* in_sizes, int n_in,
                              void* d_out, int out_size)
{
    const float* img         = (const float*)d_in[0];
    const float* title       = (const float*)d_in[1];
    const int*   mask        = (const int*)  d_in[2];
    const float* scale_img   = (const float*)d_in[3];
    const float* scale_title = (const float*)d_in[4];
    const float* w_proj      = (const float*)d_in[5];
    const float* b_proj      = (const float*)d_in[6];
    const float* w1_img      = (const float*)d_in[7];
    const float* b1_img      = (const float*)d_in[8];
    const float* w2_img      = (const float*)d_in[9];
    const float* b2_img      = (const float*)d_in[10];
    const float* w1_tit      = (const float*)d_in[11];
    const float* b1_tit      = (const float*)d_in[12];
    const float* w2_tit      = (const float*)d_in[13];
    const float* b2_tit      = (const float*)d_in[14];
    const float* ln_a_img    = (const float*)d_in[15];
    const float* ln_b_img    = (const float*)d_in[16];
    const float* ln_a_tit    = (const float*)d_in[17];
    const float* ln_b_tit    = (const float*)d_in[18];
    float* out = (float*)d_out;

    __half *attn_h, *hid_h, *G_h, *F_h, *Wh;
    cudaGetSymbolAddress((void**)&attn_h, g_attn_h);
    cudaGetSymbolAddress((void**)&hid_h,  g_hid_h);
    cudaGetSymbolAddress((void**)&G_h,    g_G_h);
    cudaGetSymbolAddress((void**)&F_h,    g_F_h);
    cudaGetSymbolAddress((void**)&Wh,     g_Wh);

    cudaFuncSetAttribute(gemm_h<512,0>,  cudaFuncAttributeMaxDynamicSharedMemorySize, GSMEM_BYTES);
    cudaFuncSetAttribute(gemm_h<512,1>,  cudaFuncAttributeMaxDynamicSharedMemorySize, GSMEM_BYTES);
    cudaFuncSetAttribute(gemm_h<2048,0>, cudaFuncAttributeMaxDynamicSharedMemorySize, GSMEM_BYTES);

    // convert all weights to half (single launch)
    f2h_all_kernel<<<(WTOTAL/4+255)/256, 256>>>(w_proj, w1_img, w2_img, w1_tit, w2_tit, Wh);

    __half* attnI = attn_h;
    __half* attnT = attn_h + (size_t)M_IMG_PAD*DD;

    attn_kernel<<<NBL*HH, 256>>>(img, title, mask, scale_img, scale_title, attnI, attnT);

    // proj for both streams (same weights both sides of the switch)
    gemm_h<512,0><<<dim3(DD/GBN, M_ALL/GBM), 256, GSMEM_BYTES>>>(
        attn_h, Wh+WOFF_P, Wh+WOFF_P, b_proj, b_proj, hid_h, M_ALL, DD);

    // ffn1 for BOTH streams in one launch (weight select at row M_IMG_PAD)
    gemm_h<512,1><<<dim3(DFF/GBN, M_ALL/GBM), 256, GSMEM_BYTES>>>(
        hid_h, Wh+WOFF_1I, Wh+WOFF_1T, b1_img, b1_tit, G_h, M_IMG_PAD, DFF);

    // ffn2 for BOTH streams in one launch
    gemm_h<2048,0><<<dim3(DD/GBN, M_ALL/GBM), 256, GSMEM_BYTES>>>(
        G_h, Wh+WOFF_2I, Wh+WOFF_2T, b2_img, b2_tit, F_h, M_IMG_PAD, DD);

    // fused LN + residual for both streams -> outputs
    ln_res_all_kernel<<<M_IMG + M_TIT, 128>>>(F_h, hid_h,
        ln_a_img, ln_b_img, ln_a_tit, ln_b_tit, out);
}

// round 13
// speedup vs baseline: 1.1539x; 1.0776x over previous
#include <cuda_runtime.h>
#include <cuda_fp16.h>
#include <cstdint>

// Problem dims
#define BB 16
#define LL 50
#define PP 49
#define TT 20
#define DD 512
#define HH 8
#define DHD 64
#define DFF 2048
#define NBL (BB*LL)            // 800
#define M_IMG (NBL*TT)         // 16000
#define M_TIT (NBL*PP)         // 39200
#define M_IMG_PAD 16128        // 126*128
#define M_TIT_PAD 39424        // 308*128
#define M_ALL (M_IMG_PAD + M_TIT_PAD)   // 55552 = 434*128

// Weight offsets in half scratch
#define WOFF_P   0
#define WOFF_1I  262144
#define WOFF_2I  1310720
#define WOFF_1T  2359296
#define WOFF_2T  3407872
#define WTOTAL   4456448

// Scratch (zero-init; pad rows never written -> stay 0)
__device__ __half g_attn_h[(size_t)M_ALL*DD];
__device__ __half g_hid_h[(size_t)M_ALL*DD];
__device__ __half g_G_h  [(size_t)M_ALL*DFF];
__device__ __half g_F_h  [(size_t)M_ALL*DD];
__device__ __half g_Wh   [WTOTAL];

// ---------------------------------------------------------------------------
// helpers
// ---------------------------------------------------------------------------
__device__ __forceinline__ void cpa(uint32_t sa, const void* g) {
    asm volatile("cp.async.cg.shared.global [%0], [%1], 16;" :: "r"(sa), "l"(g));
}
__device__ __forceinline__ void ldm4(uint32_t* r, uint32_t addr) {
    asm volatile("ldmatrix.sync.aligned.m8n8.x4.shared.b16 {%0,%1,%2,%3}, [%4];"
        : "=r"(r[0]), "=r"(r[1]), "=r"(r[2]), "=r"(r[3]) : "r"(addr));
}
__device__ __forceinline__ void mma16816(float* d, const uint32_t* a, const uint32_t* b) {
    asm volatile(
        "mma.sync.aligned.m16n8k16.row.col.f32.f16.f16.f32 "
        "{%0,%1,%2,%3},{%4,%5,%6,%7},{%8,%9},{%0,%1,%2,%3};"
        : "+f"(d[0]), "+f"(d[1]), "+f"(d[2]), "+f"(d[3])
        : "r"(a[0]), "r"(a[1]), "r"(a[2]), "r"(a[3]), "r"(b[0]), "r"(b[1]));
}
// overflow-safe fast gelu-tanh (__expf based, rel err ~1e-6)
__device__ __forceinline__ float gelu_fast(float x) {
    float x2 = x*x;
    float u  = x*(0.79788456080286536f + 0.03567740814183493f*x2);
    float au = fabsf(u);
    float e  = __expf(-2.f*au);            // (0,1], no overflow
    float th = __fdividef(1.f - e, 1.f + e);
    th = copysignf(th, u);
    return 0.5f*x*(1.f + th);
}

// ---------------------------------------------------------------------------
// fused fp32 -> fp16 convert for all 5 weight matrices
// ---------------------------------------------------------------------------
__global__ void __launch_bounds__(256) f2h_all_kernel(
    const float* __restrict__ wp, const float* __restrict__ w1i,
    const float* __restrict__ w2i, const float* __restrict__ w1t,
    const float* __restrict__ w2t, __half* __restrict__ d)
{
    int idx = (blockIdx.x*256 + threadIdx.x) * 4;
    if (idx >= WTOTAL) return;
    const float* s;
    int local;
    if (idx < WOFF_1I)      { s = wp;  local = idx - WOFF_P;  }
    else if (idx < WOFF_2I) { s = w1i; local = idx - WOFF_1I; }
    else if (idx < WOFF_1T) { s = w2i; local = idx - WOFF_2I; }
    else if (idx < WOFF_2T) { s = w1t; local = idx - WOFF_1T; }
    else                    { s = w2t; local = idx - WOFF_2T; }
    float4 v = *(const float4*)(s + local);
    __half2* p = (__half2*)(d + idx);
    p[0] = __floats2half2_rn(v.x, v.y);
    p[1] = __floats2half2_rn(v.z, v.w);
}

// ---------------------------------------------------------------------------
// Attention kernel: one block per (bl, h). fp32 math, register-tiled einsums,
// half outputs.
// ---------------------------------------------------------------------------
__global__ void __launch_bounds__(256) attn_kernel(
    const float* __restrict__ img, const float* __restrict__ tit,
    const int* __restrict__ mask,
    const float* __restrict__ scale_img, const float* __restrict__ scale_tit,
    __half* __restrict__ attnI, __half* __restrict__ attnT)
{
    __shared__ float simg[52][DHD+1];     // rows 49..51 zeroed
    __shared__ float stit[TT][DHD+1];
    __shared__ float raw[PP][TT];
    __shared__ float pimg[52][TT];        // rows 49..51 zeroed
    __shared__ float ptit[TT][PP];
    __shared__ float sci[PP];
    __shared__ float sct[TT];
    __shared__ int   smask[TT];

    int bl = blockIdx.x >> 3;
    int h  = blockIdx.x & 7;
    int tid = threadIdx.x;

    const float* ib = img + (size_t)bl*PP*DD + h*DHD;
    const float* tb = tit + (size_t)bl*TT*DD + h*DHD;

    for (int i = tid; i < PP*DHD; i += 256) { int p=i>>6, d=i&63; simg[p][d] = ib[p*DD+d]; }
    for (int i = tid; i < TT*DHD; i += 256) { int t=i>>6, d=i&63; stit[t][d] = tb[t*DD+d]; }
    // zero pad rows (simg 49..51 full row incl col 64 not needed; d<64 read only)
    for (int i = tid; i < 3*DHD; i += 256) simg[49 + i/DHD][i%DHD] = 0.f;
    for (int i = tid; i < 3*TT;  i += 256) pimg[49 + i/TT][i%TT]   = 0.f;
    if (tid < TT) { smask[tid] = mask[bl*TT+tid]; sct[tid] = scale_tit[h*TT+tid]; }
    if (tid >= 64 && tid < 64+PP) sci[tid-64] = scale_img[h*PP + (tid-64)];
    __syncthreads();

    // raw[p][t] = <img_p, tit_t> / 8   — 4p x 5t register tiles, 52 threads
    if (tid < 52) {
        int p0 = (tid >> 2) * 4;
        int t0 = (tid & 3) * 5;
        float acc[4][5];
        #pragma unroll
        for (int i = 0; i < 4; i++)
            #pragma unroll
            for (int j = 0; j < 5; j++) acc[i][j] = 0.f;
        #pragma unroll 4
        for (int d = 0; d < DHD; d++) {
            float a0 = simg[p0+0][d], a1 = simg[p0+1][d];
            float a2 = simg[p0+2][d], a3 = simg[p0+3][d];
            #pragma unroll
            for (int j = 0; j < 5; j++) {
                float b = stit[t0+j][d];
                acc[0][j] += a0*b; acc[1][j] += a1*b;
                acc[2][j] += a2*b; acc[3][j] += a3*b;
            }
        }
        #pragma unroll
        for (int i = 0; i < 4; i++)
            if (p0+i < PP)
                #pragma unroll
                for (int j = 0; j < 5; j++)
                    raw[p0+i][t0+j] = acc[i][j] * 0.125f;
    }
    __syncthreads();

    // softmaxes
    if (tid < PP) {
        int p = tid; float sc = sci[p];
        float v[TT]; float mx = -INFINITY;
        #pragma unroll
        for (int t = 0; t < TT; t++) { v[t] = smask[t] ? raw[p][t]*sc : -1e9f; mx = fmaxf(mx, v[t]); }
        float sum = 0.f;
        #pragma unroll
        for (int t = 0; t < TT; t++) { v[t] = __expf(v[t]-mx); sum += v[t]; }
        float inv = 1.f/sum;
        #pragma unroll
        for (int t = 0; t < TT; t++) pimg[p][t] = v[t]*inv;
    } else if (tid >= 64 && tid < 64+TT) {
        int t = tid-64; float sc = sct[t];
        if (smask[t]) {
            float mx = -INFINITY;
            for (int p = 0; p < PP; p++) mx = fmaxf(mx, raw[p][t]*sc);
            float sum = 0.f;
            for (int p = 0; p < PP; p++) { float e = __expf(raw[p][t]*sc - mx); ptit[t][p] = e; sum += e; }
            float inv = 1.f/sum;
            for (int p = 0; p < PP; p++) ptit[t][p] *= inv;
        } else {
            float u = 1.0f/(float)PP;
            for (int p = 0; p < PP; p++) ptit[t][p] = u;
        }
    }
    __syncthreads();

    // hid_img[t][d] = sum_p ptit[t][p]*simg[p][d]   — 4t x 4d tiles, threads 0..79
    // hid_tit[p][d] = sum_t pimg[p][t]*stit[t][d]   — 4p x 8d tiles, threads 80..183
    if (tid < 80) {
        int t0 = (tid >> 4) * 4;
        int d0 = (tid & 15) * 4;
        float acc[4][4];
        #pragma unroll
        for (int i = 0; i < 4; i++)
            #pragma unroll
            for (int j = 0; j < 4; j++) acc[i][j] = 0.f;
        for (int p = 0; p < PP; p++) {
            float a0 = ptit[t0+0][p], a1 = ptit[t0+1][p];
            float a2 = ptit[t0+2][p], a3 = ptit[t0+3][p];
            #pragma unroll
            for (int j = 0; j < 4; j++) {
                float b = simg[p][d0+j];
                acc[0][j] += a0*b; acc[1][j] += a1*b;
                acc[2][j] += a2*b; acc[3][j] += a3*b;
            }
        }
        #pragma unroll
        for (int i = 0; i < 4; i++) {
            __half* o = attnI + ((size_t)bl*TT + t0+i)*DD + h*DHD + d0;
            #pragma unroll
            for (int j = 0; j < 4; j++) o[j] = __float2half_rn(acc[i][j]);
        }
    } else if (tid < 184) {
        int id = tid - 80;
        int p0 = (id >> 3) * 4;
        int d0 = (id & 7) * 8;
        float acc[4][8];
        #pragma unroll
        for (int i = 0; i < 4; i++)
            #pragma unroll
            for (int k = 0; k < 8; k++) acc[i][k] = 0.f;
        #pragma unroll 4
        for (int t = 0; t < TT; t++) {
            float a0 = pimg[p0+0][t], a1 = pimg[p0+1][t];
            float a2 = pimg[p0+2][t], a3 = pimg[p0+3][t];
            #pragma unroll
            for (int k = 0; k < 8; k++) {
                float b = stit[t][d0+k];
                acc[0][k] += a0*b; acc[1][k] += a1*b;
                acc[2][k] += a2*b; acc[3][k] += a3*b;
            }
        }
        #pragma unroll
        for (int i = 0; i < 4; i++) {
            if (p0+i < PP) {
                __half* o = attnT + ((size_t)bl*PP + p0+i)*DD + h*DHD + d0;
                #pragma unroll
                for (int k = 0; k < 8; k++) o[k] = __float2half_rn(acc[i][k]);
            }
        }
    }
}

// ---------------------------------------------------------------------------
// fp16 mma.sync GEMM with per-row-block weight select:
//   C[M,N] = A[M,K] @ Wsel[N,K]^T + bias_sel   (Wsel = Wa if m0<Mswitch else Wb)
// Block 128x128, 8 warps (2x4), warp tile 64x32 (4x4 of m16n8k16). BK=64,
// 3-stage cp.async ring, 128B-row swizzle, ldmatrix.x4, 2 CTAs/SM.
// Register-diet: 32-bit addressing, per-step frag arrays. K compile-time.
// ---------------------------------------------------------------------------
#define GBM 128
#define GBN 128
#define GBK 64
#define STG_B 32768u                 // A 16KB + B 16KB per stage
#define NSTAGE 3
#define GSMEM_BYTES (NSTAGE*STG_B)   // 98304

template<int KT>
__device__ __forceinline__ void fill_stage(uint32_t sdst,
    const __half* fA, const __half* fW, uint32_t foff, int kcol)
{
    #pragma unroll
    for (int i = 0; i < 4; i++) {
        cpa(sdst + foff + i*4096u,            fA + kcol + i*32*KT);
        cpa(sdst + 16384u + foff + i*4096u,   fW + kcol + i*32*KT);
    }
    asm volatile("cp.async.commit_group;" ::: "memory");
}

template<int KT, int GELU_EPI>
__global__ void __launch_bounds__(256, 2) gemm_h(
    const __half* __restrict__ A,
    const __half* __restrict__ Wa, const __half* __restrict__ Wb,
    const float* __restrict__ ba,  const float* __restrict__ bb,
    __half* __restrict__ Ch, int Mswitch, int N)
{
    extern __shared__ __align__(1024) char sm[];
    uint32_t smem_base = (uint32_t)__cvta_generic_to_shared(sm);
    constexpr int nk = KT / GBK;

    int tid  = threadIdx.x;
    int warp = tid >> 5, lane = tid & 31;
    int wm = warp >> 2, wn = warp & 3;       // 2x4 warps of 64x32
    int m0i = blockIdx.y * GBM;
    int n0i = blockIdx.x * GBN;

    const __half* Ag = A + (size_t)m0i*KT;
    const __half* Wg = ((m0i >= Mswitch) ? Wb : Wa) + (size_t)n0i*KT;

    // fill-lane constants
    int fr = tid >> 3, fg = tid & 7;
    uint32_t foff = (uint32_t)((fr*8 + (fg ^ (fr & 7))) << 4);
    const __half* fA = Ag + fr*KT + fg*8;
    const __half* fW = Wg + fr*KT + fg*8;

    // ldmatrix lane constants, bases folded into xor terms
    int a_rl = lane & 15;
    int a_gs = lane >> 4;
    int b_nl = (lane & 7) | ((lane & 16) >> 1);
    int b_gs = (lane >> 3) & 1;
    uint32_t xa[4], xb[4];
    #pragma unroll
    for (int ks = 0; ks < 4; ks++) {
        xa[ks] = (uint32_t)((wm*64 + a_rl)*128) +
                 (uint32_t)((((ks*2 + a_gs) ^ (a_rl & 7))) << 4);
        xb[ks] = 16384u + (uint32_t)((wn*32 + b_nl)*128) +
                 (uint32_t)((((ks*2 + b_gs) ^ (b_nl & 7))) << 4);
    }

    float acc[4][4][4];
    #pragma unroll
    for (int mi = 0; mi < 4; mi++)
        #pragma unroll
        for (int ni = 0; ni < 4; ni++)
            #pragma unroll
            for (int e = 0; e < 4; e++) acc[mi][ni][e] = 0.f;

    // prologue: stages 0,1 (k-blocks 0,1)
    fill_stage<KT>(smem_base,          fA, fW, foff, 0);
    fill_stage<KT>(smem_base + STG_B,  fA, fW, foff, GBK);

    uint32_t stgoff = 0;
    for (int kt = 0; kt < nk; kt++) {
        if (kt == nk-1) { asm volatile("cp.async.wait_group 0;" ::: "memory"); }
        else            { asm volatile("cp.async.wait_group 1;" ::: "memory"); }
        __syncthreads();    // orders prior iter's reads before refill of that slot

        if (kt + 2 < nk) {
            uint32_t s2 = (stgoff >= STG_B) ? (stgoff - STG_B) : (stgoff + 2u*STG_B);
            fill_stage<KT>(smem_base + s2, fA, fW, foff, (kt+2)*GBK);
        }

        uint32_t sbase = smem_base + stgoff;
        #pragma unroll
        for (int ks = 0; ks < 4; ks++) {
            uint32_t a[4][4], b[2][4];
            #pragma unroll
            for (int mi = 0; mi < 4; mi++) ldm4(a[mi], sbase + xa[ks] + mi*2048u);
            #pragma unroll
            for (int j = 0; j < 2; j++)    ldm4(b[j],  sbase + xb[ks] + j*2048u);
            #pragma unroll
            for (int mi = 0; mi < 4; mi++)
                #pragma unroll
                for (int ni = 0; ni < 4; ni++)
                    mma16816(acc[mi][ni], a[mi], &b[ni>>1][(ni&1)*2]);
        }
        stgoff += STG_B; if (stgoff >= NSTAGE*STG_B) stgoff = 0;
    }

    // Epilogue: bias (+fast gelu), half2 stores, 32-bit indexing
    const float* bias = (m0i >= Mswitch) ? bb : ba;
    int q = lane >> 2, t = lane & 3;
    uint32_t rbase = (uint32_t)(m0i + wm*64 + q);
    uint32_t cbase = (uint32_t)(n0i + wn*32 + t*2);
    #pragma unroll
    for (int mi = 0; mi < 4; mi++) {
        uint32_t r0 = rbase + mi*16;
        #pragma unroll
        for (int ni = 0; ni < 4; ni++) {
            uint32_t cc = cbase + ni*8;
            float bx = bias[cc], by = bias[cc+1];
            float v00 = acc[mi][ni][0] + bx, v01 = acc[mi][ni][1] + by;
            float v10 = acc[mi][ni][2] + bx, v11 = acc[mi][ni][3] + by;
            if (GELU_EPI) {
                v00 = gelu_fast(v00); v01 = gelu_fast(v01);
                v10 = gelu_fast(v10); v11 = gelu_fast(v11);
            }
            uint32_t off = r0*(uint32_t)N + cc;
            *(__half2*)(Ch + off)                 = __floats2half2_rn(v00, v01);
            *(__half2*)(Ch + off + 8u*(uint32_t)N) = __floats2half2_rn(v10, v11);
        }
    }
}

// ---------------------------------------------------------------------------
// Fused LayerNorm (ddof=1) + residual for BOTH streams, half inputs.
// grid = M_IMG + M_TIT rows; out rows are contiguous (img then tit).
// ---------------------------------------------------------------------------
__global__ void __launch_bounds__(128) ln_res_all_kernel(
    const __half* __restrict__ F, const __half* __restrict__ hid,
    const float* __restrict__ a_img, const float* __restrict__ b_img,
    const float* __restrict__ a_tit, const float* __restrict__ b_tit,
    float* __restrict__ out)
{
    int row = blockIdx.x;
    const float* aP; const float* bP;
    size_t srow;
    if (row < M_IMG) { aP = a_img; bP = b_img; srow = (size_t)row; }
    else             { aP = a_tit; bP = b_tit; srow = (size_t)M_IMG_PAD + (row - M_IMG); }

    const __half2* x2 = (const __half2*)(F   + srow*DD);
    const __half2* h2 = (const __half2*)(hid + srow*DD);
    int tid = threadIdx.x;

    float2 v0 = __half22float2(x2[tid]);
    float2 v1 = __half22float2(x2[tid + 128]);
    float s  = v0.x + v0.y + v1.x + v1.y;
    float ss = v0.x*v0.x + v0.y*v0.y + v1.x*v1.x + v1.y*v1.y;
    #pragma unroll
    for (int o = 16; o; o >>= 1) { s += __shfl_xor_sync(~0u, s, o); ss += __shfl_xor_sync(~0u, ss, o); }
    __shared__ float sh[8];
    if ((tid & 31) == 0) { sh[tid>>5] = s; sh[4 + (tid>>5)] = ss; }
    __syncthreads();
    s  = sh[0]+sh[1]+sh[2]+sh[3];
    ss = sh[4]+sh[5]+sh[6]+sh[7];
    float mean = s * (1.f/512.f);
    float var  = fmaxf((ss - 512.f*mean*mean) * (1.f/511.f), 0.f);
    float inv  = 1.f/(sqrtf(var) + 1e-6f);

    float2 hh0 = __half22float2(h2[tid]);
    float2 hh1 = __half22float2(h2[tid + 128]);
    const float2* a2 = (const float2*)aP;
    const float2* b2 = (const float2*)bP;
    float2 A0 = a2[tid], A1 = a2[tid+128];
    float2 B0 = b2[tid], B1 = b2[tid+128];

    float2* o2 = (float2*)(out + (size_t)row*DD);
    o2[tid]     = make_float2(hh0.x + A0.x*(v0.x-mean)*inv + B0.x,
                              hh0.y + A0.y*(v0.y-mean)*inv + B0.y);
    o2[tid+128] = make_float2(hh1.x + A1.x*(v1.x-mean)*inv + B1.x,
                              hh1.y + A1.y*(v1.y-mean)*inv + B1.y);
}

// ---------------------------------------------------------------------------
// Launch
// ---------------------------------------------------------------------------
extern "C" void kernel_launch(void* const* d_in, const int* in_sizes, int n_in,
                              void* d_out, int out_size)
{
    const float* img         = (const float*)d_in[0];
    const float* title       = (const float*)d_in[1];
    const int*   mask        = (const int*)  d_in[2];
    const float* scale_img   = (const float*)d_in[3];
    const float* scale_title = (const float*)d_in[4];
    const float* w_proj      = (const float*)d_in[5];
    const float* b_proj      = (const float*)d_in[6];
    const float* w1_img      = (const float*)d_in[7];
    const float* b1_img      = (const float*)d_in[8];
    const float* w2_img      = (const float*)d_in[9];
    const float* b2_img      = (const float*)d_in[10];
    const float* w1_tit      = (const float*)d_in[11];
    const float* b1_tit      = (const float*)d_in[12];
    const float* w2_tit      = (const float*)d_in[13];
    const float* b2_tit      = (const float*)d_in[14];
    const float* ln_a_img    = (const float*)d_in[15];
    const float* ln_b_img    = (const float*)d_in[16];
    const float* ln_a_tit    = (const float*)d_in[17];
    const float* ln_b_tit    = (const float*)d_in[18];
    float* out = (float*)d_out;

    __half *attn_h, *hid_h, *G_h, *F_h, *Wh;
    cudaGetSymbolAddress((void**)&attn_h, g_attn_h);
    cudaGetSymbolAddress((void**)&hid_h,  g_hid_h);
    cudaGetSymbolAddress((void**)&G_h,    g_G_h);
    cudaGetSymbolAddress((void**)&F_h,    g_F_h);
    cudaGetSymbolAddress((void**)&Wh,     g_Wh);

    cudaFuncSetAttribute(gemm_h<512,0>,  cudaFuncAttributeMaxDynamicSharedMemorySize, GSMEM_BYTES);
    cudaFuncSetAttribute(gemm_h<512,1>,  cudaFuncAttributeMaxDynamicSharedMemorySize, GSMEM_BYTES);
    cudaFuncSetAttribute(gemm_h<2048,0>, cudaFuncAttributeMaxDynamicSharedMemorySize, GSMEM_BYTES);

    // convert all weights to half (single launch)
    f2h_all_kernel<<<(WTOTAL/4+255)/256, 256>>>(w_proj, w1_img, w2_img, w1_tit, w2_tit, Wh);

    __half* attnI = attn_h;
    __half* attnT = attn_h + (size_t)M_IMG_PAD*DD;

    attn_kernel<<<NBL*HH, 256>>>(img, title, mask, scale_img, scale_title, attnI, attnT);

    // proj for both streams (same weights both sides of the switch)
    gemm_h<512,0><<<dim3(DD/GBN, M_ALL/GBM), 256, GSMEM_BYTES>>>(
        attn_h, Wh+WOFF_P, Wh+WOFF_P, b_proj, b_proj, hid_h, M_ALL, DD);

    // ffn1 for BOTH streams in one launch (weight select at row M_IMG_PAD)
    gemm_h<512,1><<<dim3(DFF/GBN, M_ALL/GBM), 256, GSMEM_BYTES>>>(
        hid_h, Wh+WOFF_1I, Wh+WOFF_1T, b1_img, b1_tit, G_h, M_IMG_PAD, DFF);

    // ffn2 for BOTH streams in one launch
    gemm_h<2048,0><<<dim3(DD/GBN, M_ALL/GBM), 256, GSMEM_BYTES>>>(
        G_h, Wh+WOFF_2I, Wh+WOFF_2T, b2_img, b2_tit, F_h, M_IMG_PAD, DD);

    // fused LN + residual for both streams -> outputs
    ln_res_all_kernel<<<M_IMG + M_TIT, 128>>>(F_h, hid_h,
        ln_a_img, ln_b_img, ln_a_tit, ln_b_tit, out);
}